// round 2
// baseline (speedup 1.0000x reference)
#include <cuda_runtime.h>
#include <math.h>

#define SQ 2048
#define NH 16
#define ID 128
#define ROPE 64
#define NOPE 128
#define VDIM 128
#define KVL 512
#define QD 576
#define HIDD 2048
#define QLORA 1536
#define TOPKK 1024
#define EPSV 1e-6f
#define SCALV 0.08838834764831845f  /* 128^-0.5 */

// ---------------- scratch (device globals; no runtime allocation) ----------------
__device__ float g_ckv[SQ * ID];
__device__ float g_ik[SQ * ID];
__device__ float g_ql[SQ * NH * ID];
__device__ float g_iq[SQ * NH * ID];
__device__ float g_wt[SQ * NH];
__device__ float g_w[SQ * NH];
__device__ float g_q[SQ * NH * QD];
__device__ float g_kv[SQ * QD];
__device__ float g_score[SQ * SQ];
__device__ unsigned char g_mask[SQ * SQ];
__device__ float g_P[(size_t)NH * SQ * SQ];
__device__ float g_ao[(size_t)NH * SQ * KVL];

// ---------------- generic tiled SGEMM: C = A @ B(^T) ----------------
// A: M x K row-major (lda). TRANSB: B is N x K row-major (ldb=K-stride); else B is K x N (ldb=N-stride).
// CAUSAL_N: skip output tiles fully above the diagonal (N dim indexes keys).
// CAUSAL_K: limit K loop to k <= row_max (K dim indexes keys).
template <int TRANSB, int CAUSAL_N, int CAUSAL_K>
__global__ void sgemm_k(const float* __restrict__ Ag, const float* __restrict__ Bg,
                        float* __restrict__ Cg, int M, int N, int K,
                        int lda, int ldb, int ldc,
                        long aB, long bB, long cB) {
    constexpr int BM = 64, BN = 64, BK = 16;
    int bm = blockIdx.y, bn = blockIdx.x;
    if (CAUSAL_N && bn * BN > bm * BM + BM - 1) return;
    const float* A = Ag + (long)blockIdx.z * aB;
    const float* B = Bg + (long)blockIdx.z * bB;
    float* C = Cg + (long)blockIdx.z * cB;
    __shared__ float As[BK][BM];
    __shared__ float Bs[BK][BN];
    int tid = threadIdx.x;
    int tx = tid & 15, ty = tid >> 4;
    float acc[4][4];
#pragma unroll
    for (int i = 0; i < 4; i++)
#pragma unroll
        for (int j = 0; j < 4; j++) acc[i][j] = 0.f;
    int kEnd = K;
    if (CAUSAL_K) kEnd = min(K, bm * BM + BM);
    int arow = tid >> 2, akq = (tid & 3) << 2;
    for (int k0 = 0; k0 < kEnd; k0 += BK) {
        float4 av = *(const float4*)(A + (long)(bm * BM + arow) * lda + (k0 + akq));
        As[akq + 0][arow] = av.x; As[akq + 1][arow] = av.y;
        As[akq + 2][arow] = av.z; As[akq + 3][arow] = av.w;
        if (TRANSB) {
            int bl = tid >> 2;
            int brow = bn * BN + bl;
            int kq = (tid & 3) << 2;
            float4 bv = make_float4(0.f, 0.f, 0.f, 0.f);
            if (brow < N) bv = *(const float4*)(B + (long)brow * ldb + (k0 + kq));
            Bs[kq + 0][bl] = bv.x; Bs[kq + 1][bl] = bv.y;
            Bs[kq + 2][bl] = bv.z; Bs[kq + 3][bl] = bv.w;
        } else {
            int bk = tid >> 4;
            int bc = (tid & 15) << 2;
            int bcol = bn * BN + bc;
            float4 bv = make_float4(0.f, 0.f, 0.f, 0.f);
            if (bcol < N) bv = *(const float4*)(B + (long)(k0 + bk) * ldb + bcol);
            Bs[bk][bc + 0] = bv.x; Bs[bk][bc + 1] = bv.y;
            Bs[bk][bc + 2] = bv.z; Bs[bk][bc + 3] = bv.w;
        }
        __syncthreads();
#pragma unroll
        for (int kk = 0; kk < BK; kk++) {
            float4 a4 = *(const float4*)&As[kk][ty << 2];
            float4 b4 = *(const float4*)&Bs[kk][tx << 2];
            float a[4] = {a4.x, a4.y, a4.z, a4.w};
            float b[4] = {b4.x, b4.y, b4.z, b4.w};
#pragma unroll
            for (int i = 0; i < 4; i++)
#pragma unroll
                for (int j = 0; j < 4; j++) acc[i][j] += a[i] * b[j];
        }
        __syncthreads();
    }
#pragma unroll
    for (int i = 0; i < 4; i++) {
        int row = bm * BM + (ty << 2) + i;
#pragma unroll
        for (int j = 0; j < 4; j++) {
            int col = bn * BN + (tx << 2) + j;
            if (col < N) C[(long)row * ldc + col] = acc[i][j];
        }
    }
}

// ---------------- index_k: rope(interleaved, deinterleaved output) + rmsnorm ----------------
__global__ void indexk_kernel(const float* __restrict__ ckv, const float* __restrict__ cosb,
                              const float* __restrict__ sinb, const float* __restrict__ knorm,
                              float* __restrict__ ik) {
    int s = blockIdx.x, j = threadIdx.x;  // 128 threads
    __shared__ float sh[128];
    __shared__ float red[128];
    sh[j] = ckv[s * 128 + j];
    __syncthreads();
    float x = (j >= 64) ? sh[j] * sh[j] : 0.f;
    red[j] = x;
    __syncthreads();
    for (int t = 64; t > 0; t >>= 1) {
        if (j < t) red[j] += red[j + t];
        __syncthreads();
    }
    float rstd = rsqrtf(red[0] / 64.f + EPSV);
    float o;
    if (j < 64) {
        float c = cosb[s * 64 + j], si = sinb[s * 64 + j];  // cos/sin halves duplicated
        int jj = j & 31;
        float e = sh[2 * jj], od = sh[2 * jj + 1];
        o = (j < 32) ? (e * c - od * si) : (od * c + e * si);
    } else {
        o = sh[j] * rstd * knorm[j - 64];
    }
    ik[s * 128 + j] = o;
}

// ---------------- index_q: rope first 64 of each 128-chunk ----------------
__global__ void indexq_kernel(const float* __restrict__ ql, const float* __restrict__ cosb,
                              const float* __restrict__ sinb, float* __restrict__ iq) {
    int s = blockIdx.x;
    int tid = threadIdx.x;  // 256
    __shared__ float sh[2048];
    for (int i = tid; i < 2048; i += 256) sh[i] = ql[(long)s * 2048 + i];
    __syncthreads();
    for (int i = tid; i < 2048; i += 256) {
        int h = i >> 7, j = i & 127;
        float o;
        if (j < 64) {
            int jj = j & 31;
            float c = cosb[s * 64 + j], si = sinb[s * 64 + j];
            float e = sh[h * 128 + 2 * jj], od = sh[h * 128 + 2 * jj + 1];
            o = (j < 32) ? (e * c - od * si) : (od * c + e * si);
        } else {
            o = sh[h * 128 + j];
        }
        iq[(long)s * 2048 + i] = o;
    }
}

__global__ void absbias_kernel(const float* __restrict__ wt, const float* __restrict__ b,
                               float* __restrict__ w) {
    int i = blockIdx.x * 256 + threadIdx.x;
    if (i < SQ * NH) w[i] = fabsf(wt[i] + b[i & 15]);
}

__global__ void qrot_kernel(const float* __restrict__ qr, float* __restrict__ q) {
    int i = blockIdx.x * 256 + threadIdx.x;
    if (i >= NH * SQ * ROPE) return;
    int h = i / (SQ * ROPE);
    int r = i % (SQ * ROPE);
    int s = r / ROPE, j = r % ROPE;
    q[((long)s * NH + h) * QD + KVL + j] = qr[i];
}

__global__ void kvbuild_kernel(const float* __restrict__ kp, const float* __restrict__ kr,
                               float* __restrict__ kv) {
    int i = blockIdx.x * 256 + threadIdx.x;
    if (i >= SQ * QD) return;
    int s = i / QD, j = i % QD;
    kv[i] = (j < KVL) ? kp[s * KVL + j] : kr[s * ROPE + (j - KVL)];
}

// ---------------- indexer score: score[q,k] = SCAL * sum_h w[q,h]*relu(iq[q,h]·ik[k]) ----------------
__global__ void idx_score_kernel(const float* __restrict__ iq, const float* __restrict__ ik,
                                 const float* __restrict__ w, float* __restrict__ score) {
    int bq = blockIdx.y, bk = blockIdx.x;
    if (bk * 32 > bq * 32 + 31) return;  // strictly-above-diagonal tiles never read
    __shared__ float iqs[32][132];
    __shared__ float iks[32][132];
    __shared__ float ws[32][16];
    int tid = threadIdx.x;  // 256
    for (int idx = tid; idx < 32 * 128; idx += 256) {
        int r = idx >> 7, c = idx & 127;
        iks[r][c] = ik[(bk * 32 + r) * 128 + c];
    }
    for (int idx = tid; idx < 32 * 16; idx += 256) {
        int r = idx >> 4, c = idx & 15;
        ws[r][c] = w[(bq * 32 + r) * 16 + c];
    }
    int tx = tid & 15, ty = tid >> 4;
    int q0 = ty * 2, q1 = q0 + 1, k0 = tx * 2, k1 = k0 + 1;
    float s00 = 0, s01 = 0, s10 = 0, s11 = 0;
    for (int h = 0; h < 16; h++) {
        __syncthreads();
        for (int idx = tid; idx < 32 * 128; idx += 256) {
            int r = idx >> 7, c = idx & 127;
            iqs[r][c] = iq[((long)(bq * 32 + r) * 16 + h) * 128 + c];
        }
        __syncthreads();
        float d00 = 0, d01 = 0, d10 = 0, d11 = 0;
#pragma unroll 4
        for (int d = 0; d < 128; d++) {
            float a0 = iqs[q0][d], a1 = iqs[q1][d];
            float b0 = iks[k0][d], b1 = iks[k1][d];
            d00 += a0 * b0; d01 += a0 * b1;
            d10 += a1 * b0; d11 += a1 * b1;
        }
        float w0 = ws[q0][h], w1 = ws[q1][h];
        s00 += w0 * fmaxf(d00, 0.f); s01 += w0 * fmaxf(d01, 0.f);
        s10 += w1 * fmaxf(d10, 0.f); s11 += w1 * fmaxf(d11, 0.f);
    }
    long rq0 = (long)(bq * 32 + q0) * SQ, rq1 = (long)(bq * 32 + q1) * SQ;
    score[rq0 + bk * 32 + k0] = s00 * SCALV;
    score[rq0 + bk * 32 + k1] = s01 * SCALV;
    score[rq1 + bk * 32 + k0] = s10 * SCALV;
    score[rq1 + bk * 32 + k1] = s11 * SCALV;
}

// ---------------- per-query top-1024 via radix select (scores are all >= 0) ----------------
__global__ void topk_kernel(const float* __restrict__ score, unsigned char* __restrict__ mask) {
    int q = blockIdx.x;
    int n = q + 1;
    int tid = threadIdx.x;  // 256
    unsigned char* mrow = mask + (long)q * SQ;
    if (q < TOPKK) {  // all causal keys selected
        for (int k = tid; k < SQ; k += 256) mrow[k] = (k <= q) ? 1 : 0;
        return;
    }
    const float* srow = score + (long)q * SQ;
    __shared__ unsigned int sbits[SQ];
    __shared__ int hist[256];
    __shared__ unsigned int sh_prefix;
    __shared__ int sh_kk;
    for (int k = tid; k < n; k += 256) sbits[k] = __float_as_uint(srow[k]);
    if (tid == 0) { sh_prefix = 0u; sh_kk = TOPKK; }
    __syncthreads();
    for (int pass = 0; pass < 4; pass++) {
        int shift = 24 - 8 * pass;
        if (tid < 256) hist[tid] = 0;
        __syncthreads();
        unsigned int pfx = sh_prefix;
        for (int k = tid; k < n; k += 256) {
            unsigned int v = sbits[k];
            if ((unsigned int)(((unsigned long long)v) >> (shift + 8)) == pfx)
                atomicAdd(&hist[(v >> shift) & 255], 1);
        }
        __syncthreads();
        if (tid == 0) {
            int kk = sh_kk;
            int d = 255;
            for (; d >= 0; d--) {
                if (kk <= hist[d]) break;
                kk -= hist[d];
            }
            sh_prefix = (pfx << 8) | (unsigned int)d;
            sh_kk = kk;
        }
        __syncthreads();
    }
    unsigned int T = sh_prefix;
    int kk = sh_kk;  // number of ties (== T) to keep, lowest index first (matches lax.top_k)
    for (int k = tid; k < SQ; k += 256) {
        unsigned char m = 0;
        if (k < n) {
            unsigned int v = sbits[k];
            if (v > T) m = 1;
            else if (v == T) {
                int rank = 0;
                for (int j = 0; j < k; j++) rank += (sbits[j] == T) ? 1 : 0;
                m = (rank < kk) ? 1 : 0;
            }
        }
        mrow[k] = m;
    }
}

// ---------------- masked softmax over keys (writes probabilities, 0 where masked) ----------------
__global__ void softmax_kernel(float* __restrict__ P, const unsigned char* __restrict__ mask) {
    int q = blockIdx.x, h = blockIdx.y;
    float* row = P + ((long)h * SQ + q) * SQ;
    const unsigned char* mrow = mask + (long)q * SQ;
    int tid = threadIdx.x;  // 256
    float v[8];
    unsigned char m[8];
    float mx = -1e30f;
#pragma unroll
    for (int i = 0; i < 8; i++) {
        int k = i * 256 + tid;
        m[i] = mrow[k];
        float val = m[i] ? row[k] * SCALV : -1e30f;
        v[i] = val;
        mx = fmaxf(mx, val);
    }
    __shared__ float red[256];
    red[tid] = mx;
    __syncthreads();
    for (int t = 128; t > 0; t >>= 1) {
        if (tid < t) red[tid] = fmaxf(red[tid], red[tid + t]);
        __syncthreads();
    }
    mx = red[0];
    __syncthreads();
    float sum = 0.f;
#pragma unroll
    for (int i = 0; i < 8; i++) {
        if (m[i]) { v[i] = __expf(v[i] - mx); sum += v[i]; }
        else v[i] = 0.f;
    }
    red[tid] = sum;
    __syncthreads();
    for (int t = 128; t > 0; t >>= 1) {
        if (tid < t) red[tid] += red[tid + t];
        __syncthreads();
    }
    float inv = 1.f / red[0];
#pragma unroll
    for (int i = 0; i < 8; i++) row[i * 256 + tid] = v[i] * inv;
}

// ---------------- launch ----------------
extern "C" void kernel_launch(void* const* d_in, const int* in_sizes, int n_in,
                              void* d_out, int out_size) {
    const float* q_latent = (const float*)d_in[0];
    const float* hidden   = (const float*)d_in[1];
    const float* cosb     = (const float*)d_in[2];
    const float* sinb     = (const float*)d_in[3];
    const float* q_pass   = (const float*)d_in[4];
    const float* q_rot    = (const float*)d_in[5];
    const float* k_pass   = (const float*)d_in[6];
    const float* k_rot    = (const float*)d_in[7];
    /* d_in[8] = position_ids (unused by reference) */
    const float* kv_b     = (const float*)d_in[9];
    const float* wq_b     = (const float*)d_in[10];
    const float* wk       = (const float*)d_in[11];
    const float* knorm    = (const float*)d_in[12];
    const float* wproj    = (const float*)d_in[13];
    const float* wproj_b  = (const float*)d_in[14];
    float* out = (float*)d_out;

    float *ckv, *ik, *ql, *iq, *wt, *w, *q, *kv, *score, *P, *ao;
    unsigned char* mask;
    cudaGetSymbolAddress((void**)&ckv, g_ckv);
    cudaGetSymbolAddress((void**)&ik, g_ik);
    cudaGetSymbolAddress((void**)&ql, g_ql);
    cudaGetSymbolAddress((void**)&iq, g_iq);
    cudaGetSymbolAddress((void**)&wt, g_wt);
    cudaGetSymbolAddress((void**)&w, g_w);
    cudaGetSymbolAddress((void**)&q, g_q);
    cudaGetSymbolAddress((void**)&kv, g_kv);
    cudaGetSymbolAddress((void**)&score, g_score);
    cudaGetSymbolAddress((void**)&mask, g_mask);
    cudaGetSymbolAddress((void**)&P, g_P);
    cudaGetSymbolAddress((void**)&ao, g_ao);

    // 1. ckv = hidden @ wk^T   (2048x128)
    sgemm_k<1, 0, 0><<<dim3(2, 32, 1), 256>>>(hidden, wk, ckv, SQ, ID, HIDD,
                                              HIDD, HIDD, ID, 0, 0, 0);
    // 2. index_k (rope + rmsnorm)
    indexk_kernel<<<SQ, 128>>>(ckv, cosb, sinb, knorm, ik);
    // 3. ql = q_latent @ wq_b^T   (2048x2048)
    sgemm_k<1, 0, 0><<<dim3(32, 32, 1), 256>>>(q_latent, wq_b, ql, SQ, NH * ID, QLORA,
                                               QLORA, QLORA, NH * ID, 0, 0, 0);
    // 4. index_q (rope on first 64 per head)
    indexq_kernel<<<SQ, 256>>>(ql, cosb, sinb, iq);
    // 5. w = |hidden @ wproj^T + b|
    sgemm_k<1, 0, 0><<<dim3(1, 32, 1), 256>>>(hidden, wproj, wt, SQ, NH, HIDD,
                                              HIDD, HIDD, NH, 0, 0, 0);
    absbias_kernel<<<(SQ * NH + 255) / 256, 256>>>(wt, wproj_b, w);
    // 6. q_abs[h] = q_pass[h] @ k_b[h]   (batched NN, z=16) -> q[:, :, 0:512]
    sgemm_k<0, 0, 0><<<dim3(8, 32, 16), 256>>>(q_pass, kv_b, q, SQ, KVL, NOPE,
                                               NOPE, KVL, NH * QD,
                                               (long)SQ * NOPE, (long)256 * KVL, (long)QD);
    qrot_kernel<<<(NH * SQ * ROPE + 255) / 256, 256>>>(q_rot, q);
    kvbuild_kernel<<<(SQ * QD + 255) / 256, 256>>>(k_pass, k_rot, kv);
    // 7. indexer scores (causal tiles only)
    idx_score_kernel<<<dim3(64, 64), 256>>>(iq, ik, w, score);
    // 8. top-1024 mask per query
    topk_kernel<<<SQ, 256>>>(score, mask);
    // 9. logits[h] = q[:,h,:] @ kv^T   (batched NT, causal-N skip)
    sgemm_k<1, 1, 0><<<dim3(32, 32, 16), 256>>>(q, kv, P, SQ, SQ, QD,
                                                NH * QD, QD, SQ,
                                                (long)QD, 0L, (long)SQ * SQ);
    // 10. masked softmax
    softmax_kernel<<<dim3(SQ, NH), 256>>>(P, mask);
    // 11. attn_out[h] = P[h] @ kv[:, :512]   (batched NN, causal-K limit)
    sgemm_k<0, 0, 1><<<dim3(8, 32, 16), 256>>>(P, kv, ao, SQ, KVL, SQ,
                                               SQ, QD, KVL,
                                               (long)SQ * SQ, 0L, (long)SQ * KVL);
    // 12. out[s,h,:] = attn_out[h,s,:] @ v_b[h]^T   (batched NT)
    sgemm_k<1, 0, 0><<<dim3(2, 32, 16), 256>>>(ao, kv_b + NOPE * KVL, out, SQ, VDIM, KVL,
                                               KVL, KVL, NH * VDIM,
                                               (long)SQ * KVL, (long)256 * KVL, (long)VDIM);
}